// round 14
// baseline (speedup 1.0000x reference)
#include <cuda_runtime.h>
#include <cuda_bf16.h>
#include <math.h>

// ---------------------------------------------------------------------------
// Causal self-attention block via mma.sync (HMMA bf16) on sm_103.
// fp32 emulation by SEGMENTED 2-plane bf16 split (H,L over original K);
// GEMM computes AhBh + AlBh + AhBl (drops only AlBl ~2^-18).
// R13: 256x128 CTA tile, 256 threads / 8 warps (64x64 warp tiles),
// 64-k superchunks with ONE mbarrier wait each (4x amortization of the
// ~200cyc/warp per-chunk tax), 2-stage 192KB pipeline, 1 CTA/SM.
// ---------------------------------------------------------------------------

static const int Bb = 4, T = 2048, C = 1024;
static const int M = Bb * T;          // 8192

#define TILE32 8192                   // gmem atom: 128 rows x 32 k x 2B

// fp32 intermediates
__device__ float g_att[(size_t)4 * 2048 * 2048];
// (H,L) bf16 planes, tiled [row_stripe(128)][chunk(32k)][8KB swizzled]
__device__ __nv_bfloat16 g_xH [(size_t)8192 * 1024];
__device__ __nv_bfloat16 g_xL [(size_t)8192 * 1024];
__device__ __nv_bfloat16 g_wqH[(size_t)3072 * 1024];
__device__ __nv_bfloat16 g_wqL[(size_t)3072 * 1024];
__device__ __nv_bfloat16 g_wpH[(size_t)1024 * 1024];
__device__ __nv_bfloat16 g_wpL[(size_t)1024 * 1024];
__device__ __nv_bfloat16 g_qH [(size_t)8192 * 1024];
__device__ __nv_bfloat16 g_qL [(size_t)8192 * 1024];
__device__ __nv_bfloat16 g_kH [(size_t)8192 * 1024];
__device__ __nv_bfloat16 g_kL [(size_t)8192 * 1024];
__device__ __nv_bfloat16 g_vH [(size_t)8192 * 1024];
__device__ __nv_bfloat16 g_vL [(size_t)8192 * 1024];
__device__ __nv_bfloat16 g_vwH[(size_t)4 * 1024 * 2048];
__device__ __nv_bfloat16 g_vwL[(size_t)4 * 1024 * 2048];
__device__ __nv_bfloat16 g_aH [(size_t)8192 * 2048];
__device__ __nv_bfloat16 g_aL [(size_t)8192 * 2048];

// swizzle for 64-byte rows (32 bf16): 16B slot c (0..3) -> c ^ ((r>>1)&3)
#define SWB32(r, c) ((unsigned)((r) * 64 + ((((c) ^ (((r) >> 1) & 3)) & 3) << 4)))

__device__ __forceinline__ void ldm4(unsigned* r, unsigned addr) {
    asm volatile("ldmatrix.sync.aligned.m8n8.x4.shared.b16 {%0,%1,%2,%3}, [%4];"
        : "=r"(r[0]), "=r"(r[1]), "=r"(r[2]), "=r"(r[3]) : "r"(addr));
}
__device__ __forceinline__ void mma16816(float* d, const unsigned* a,
                                         unsigned b0, unsigned b1) {
    asm volatile(
        "mma.sync.aligned.m16n8k16.row.col.f32.bf16.bf16.f32 "
        "{%0,%1,%2,%3}, {%4,%5,%6,%7}, {%8,%9}, {%0,%1,%2,%3};"
        : "+f"(d[0]), "+f"(d[1]), "+f"(d[2]), "+f"(d[3])
        : "r"(a[0]), "r"(a[1]), "r"(a[2]), "r"(a[3]), "r"(b0), "r"(b1));
}
__device__ __forceinline__ void bulk8k(unsigned sdst, const void* g, unsigned mb) {
    unsigned sz = TILE32;
    asm volatile(
        "cp.async.bulk.shared::cluster.global.mbarrier::complete_tx::bytes "
        "[%0], [%1], %2, [%3];"
        :: "r"(sdst), "l"(__cvta_generic_to_global(g)), "r"(sz), "r"(mb)
        : "memory");
}
__device__ __forceinline__ void mbar_wait(unsigned mbar, unsigned parity) {
    asm volatile(
        "{\n\t.reg .pred P;\n\t"
        "LW_%=:\n\t"
        "mbarrier.try_wait.parity.acquire.cta.shared::cta.b64 P, [%0], %1, 0x989680;\n\t"
        "@P bra.uni LD_%=;\n\t"
        "bra.uni LW_%=;\n\t"
        "LD_%=:\n\t}"
        :: "r"(mbar), "r"(parity) : "memory");
}
__device__ __forceinline__ void mbar_arrive(unsigned mbar) {
    asm volatile("mbarrier.arrive.release.cta.shared.b64 _, [%0];"
                 :: "r"(mbar) : "memory");
}

__device__ __forceinline__ void split2(float v, unsigned short& h, unsigned short& l) {
    __nv_bfloat16 hb = __float2bfloat16(v);
    __nv_bfloat16 lb = __float2bfloat16(v - __bfloat162float(hb));
    h = __bfloat16_as_ushort(hb);
    l = __bfloat16_as_ushort(lb);
}

// stage: AH 32KB | AL 32KB | BH 16KB | BL 16KB
#define STAGE_BYTES 98304
#define NSTG 2
#define GEMM_SMEM (NSTG * STAGE_BYTES + 128)   // 196736

// ---------------------------------------------------------------------------
// D[256-tile, 128-tile] = alpha*(AhBh + AlBh + AhBl) (+bias), planes tiled.
// 256 threads, 8 warps: wm = wid>>1 (0..3, 64-row band), wn = wid&1.
// emode 0: fp32 out (Cf); emode 1: plane out D1;
// emode 2: qkv triple -> D1 (q), D2 (k), D3 (v) plane pairs.
// ---------------------------------------------------------------------------
__global__ void __launch_bounds__(256, 1)
hmma_gemm(const char* __restrict__ AH, const char* __restrict__ AL,
          const char* __restrict__ BH, const char* __restrict__ BL,
          float* __restrict__ Cf,
          char* __restrict__ D1H, char* __restrict__ D1L,
          char* __restrict__ D2H, char* __restrict__ D2L,
          char* __restrict__ D3H, char* __restrict__ D3L,
          int ncha, int nchb, int ldcf, int nchc,
          long long sAt, long long sBt, long long sC,
          float alpha, const float* __restrict__ bias,
          int causal_skip, int klimit, int K, int emode)
{
    const int row0 = blockIdx.y * 256;
    const int col0 = blockIdx.x * 128;
    if (causal_skip && col0 > row0 + 128) return;        // fully-masked tiles
    const int kend = klimit ? min(K, row0 + 256) : K;
    const int nsch = kend >> 6;                          // 64-k superchunks

    const long long aoff = ((long long)blockIdx.z * sAt + (row0 >> 7) * ncha) * TILE32;
    const long long boff = ((long long)blockIdx.z * sBt + (col0 >> 7) * nchb) * TILE32;
    AH += aoff; AL += aoff; BH += boff; BL += boff;

    extern __shared__ __align__(128) unsigned char smem[];
    const unsigned sb = (unsigned)__cvta_generic_to_shared(smem);
    const unsigned mbF = sb + NSTG * STAGE_BYTES;        // full barriers
    const unsigned mbE = mbF + 8 * NSTG;                 // empty barriers

    const int tid = threadIdx.x;
    const int lane = tid & 31;
    const int wid = tid >> 5;          // 0..7
    const int wm = wid >> 1;           // 0..3 -> 64-row band of 256
    const int wn = wid & 1;            // 0..1 -> 64-col half

    if (tid == 0) {
        #pragma unroll
        for (int s = 0; s < NSTG; s++) {
            asm volatile("mbarrier.init.shared.b64 [%0], 1;"
                         :: "r"(mbF + 8 * s) : "memory");
            asm volatile("mbarrier.init.shared.b64 [%0], 256;"
                         :: "r"(mbE + 8 * s) : "memory");
        }
    }
    __syncthreads();

    float acc[4][8][4];
    #pragma unroll
    for (int i = 0; i < 4; i++)
        #pragma unroll
        for (int j = 0; j < 8; j++)
            #pragma unroll
            for (int k = 0; k < 4; k++) acc[i][j][k] = 0.f;

    // tid0: load superchunk j into stage j&1 (12 x 8KB bulk copies)
    auto bulk_load = [&](int j) {
        const int st = j & 1;
        const unsigned mb = mbF + 8 * st;
        asm volatile("mbarrier.arrive.expect_tx.shared.b64 _, [%0], %1;"
                     :: "r"(mb), "r"((unsigned)STAGE_BYTES) : "memory");
        const unsigned s0 = sb + st * STAGE_BYTES;
        #pragma unroll
        for (int sx = 0; sx < 2; sx++)          // A row-stripes
            #pragma unroll
            for (int jc = 0; jc < 2; jc++) {    // 32-k halves
                const size_t at = ((size_t)sx * ncha + 2 * j + jc) * TILE32;
                const unsigned d = s0 + sx * 16384 + jc * 8192;
                bulk8k(d,         AH + at, mb);
                bulk8k(d + 32768, AL + at, mb);
            }
        #pragma unroll
        for (int jc = 0; jc < 2; jc++) {
            const size_t bt = (size_t)(2 * j + jc) * TILE32;
            const unsigned d = s0 + 65536 + jc * 8192;
            bulk8k(d,         BH + bt, mb);
            bulk8k(d + 16384, BL + bt, mb);
        }
    };

    const unsigned a_stripe = (wm >> 1) * 16384;         // warp's A stripe
    auto compute = [&](int j) {
        const int st = j & 1;
        const unsigned s0 = sb + st * STAGE_BYTES;
        mbar_wait(mbF + 8 * st, (j >> 1) & 1);
        #pragma unroll
        for (int s = 0; s < 4; s++) {                    // four k16 slices
            const int q = 2 * s + (lane >> 4);           // 16B slot 0..7
            const unsigned koff = (unsigned)(q >> 2) * 8192;
            const int sl = q & 3;
            unsigned AhF[4][4], AlF[4][4], BhF[4][4], BlF[4][4];
            #pragma unroll
            for (int mb = 0; mb < 4; mb++) {
                const int mr = (wm & 1) * 64 + mb * 16 + (lane & 15);
                ldm4(AhF[mb], s0 + a_stripe + koff + SWB32(mr, sl));
            }
            #pragma unroll
            for (int nb = 0; nb < 4; nb++) {
                const int nr = wn * 64 + nb * 16 + (lane & 15);
                ldm4(BhF[nb], s0 + 65536 + koff + SWB32(nr, sl));
            }
            #pragma unroll
            for (int mb = 0; mb < 4; mb++)
                #pragma unroll
                for (int nb = 0; nb < 4; nb++) {
                    mma16816(acc[mb][nb * 2 + 0], AhF[mb], BhF[nb][0], BhF[nb][2]);
                    mma16816(acc[mb][nb * 2 + 1], AhF[mb], BhF[nb][1], BhF[nb][3]);
                }
            #pragma unroll
            for (int mb = 0; mb < 4; mb++) {
                const int mr = (wm & 1) * 64 + mb * 16 + (lane & 15);
                ldm4(AlF[mb], s0 + 32768 + a_stripe + koff + SWB32(mr, sl));
            }
            #pragma unroll
            for (int mb = 0; mb < 4; mb++)
                #pragma unroll
                for (int nb = 0; nb < 4; nb++) {
                    mma16816(acc[mb][nb * 2 + 0], AlF[mb], BhF[nb][0], BhF[nb][2]);
                    mma16816(acc[mb][nb * 2 + 1], AlF[mb], BhF[nb][1], BhF[nb][3]);
                }
            #pragma unroll
            for (int nb = 0; nb < 4; nb++) {
                const int nr = wn * 64 + nb * 16 + (lane & 15);
                ldm4(BlF[nb], s0 + 81920 + koff + SWB32(nr, sl));
            }
            if (s == 3)                    // last smem read of this stage
                mbar_arrive(mbE + 8 * st);
            #pragma unroll
            for (int mb = 0; mb < 4; mb++)
                #pragma unroll
                for (int nb = 0; nb < 4; nb++) {
                    mma16816(acc[mb][nb * 2 + 0], AhF[mb], BlF[nb][0], BlF[nb][2]);
                    mma16816(acc[mb][nb * 2 + 1], AhF[mb], BlF[nb][1], BlF[nb][3]);
                }
        }
    };

    if (tid == 0) bulk_load(0);
    for (int i = 0; i < nsch; i++) {
        if (tid == 0 && i + 1 < nsch) {
            if (i >= 1)   // stage (i+1)&1 last used by superchunk i-1
                mbar_wait(mbE + 8 * ((i + 1) & 1), ((i - 1) >> 1) & 1);
            bulk_load(i + 1);
        }
        compute(i);
    }

    // ----- epilogue -----
    char *dH = 0, *dL = 0;
    int colr = col0;
    float* df = 0;
    long long ztile = 0;
    if (emode == 0) {
        df = Cf + (long long)blockIdx.z * sC;
    } else if (emode == 1) {
        dH = D1H; dL = D1L; ztile = (long long)blockIdx.z * sC;   // sC in tiles
    } else {                                  // qkv triple
        if (col0 < 1024)      { dH = D1H; dL = D1L; colr = col0; }
        else if (col0 < 2048) { dH = D2H; dL = D2L; colr = col0 - 1024; }
        else                  { dH = D3H; dL = D3L; colr = col0 - 2048; }
    }

    const int cbase = wn * 64 + 2 * (lane & 3);
    #pragma unroll
    for (int mb = 0; mb < 4; mb++) {
        #pragma unroll
        for (int half = 0; half < 2; half++) {
            const int r = row0 + wm * 64 + mb * 16 + (lane >> 2) + half * 8;
            const long long tb = dH ? (ztile + (long long)(r >> 7) * nchc) * TILE32 : 0;
            const int lr = r & 127;
            #pragma unroll
            for (int nb = 0; nb < 8; nb++) {
                const int cr = colr + cbase + nb * 8;    // region-relative (even)
                const int ca = col0 + cbase + nb * 8;    // absolute (bias)
                float vx = acc[mb][nb][half * 2 + 0] * alpha;
                float vy = acc[mb][nb][half * 2 + 1] * alpha;
                if (bias) { vx += bias[ca]; vy += bias[ca + 1]; }
                if (dH) {
                    unsigned short hx, lx, hy, ly;
                    split2(vx, hx, lx);
                    split2(vy, hy, ly);
                    const int byte = 2 * cr;             // multiple of 4
                    const unsigned off = (unsigned)(byte >> 6) * TILE32
                                       + SWB32(lr, (byte & 63) >> 4) + (byte & 15);
                    *(unsigned*)(dH + tb + off) = (unsigned)hx | ((unsigned)hy << 16);
                    *(unsigned*)(dL + tb + off) = (unsigned)lx | ((unsigned)ly << 16);
                } else {
                    *(float2*)(df + (long long)r * ldcf + cr) = make_float2(vx, vy);
                }
            }
        }
    }
}

// ---------------------------------------------------------------------------
// fp32 -> (h,l) planes, tiled+swizzled output
// ---------------------------------------------------------------------------
__global__ void split2_kernel(const float* __restrict__ in,
                              __nv_bfloat16* __restrict__ outH,
                              __nv_bfloat16* __restrict__ outL,
                              int R, int Cin, int ld)
{
    const int c8n = Cin >> 3;
    long long idx = (long long)blockIdx.x * blockDim.x + threadIdx.x;
    if (idx >= (long long)R * c8n) return;
    const int r = (int)(idx / c8n);
    const int c = (int)(idx - (long long)r * c8n) * 8;

    const float4 v0 = *(const float4*)(in + (long long)r * ld + c);
    const float4 v1 = *(const float4*)(in + (long long)r * ld + c + 4);
    float f[8] = {v0.x, v0.y, v0.z, v0.w, v1.x, v1.y, v1.z, v1.w};

    alignas(16) unsigned short h[8], l[8];
    #pragma unroll
    for (int j = 0; j < 8; j++) split2(f[j], h[j], l[j]);

    const int nch = Cin >> 5;
    const size_t base = (size_t)(r >> 7) * nch * TILE32;
    const int lr = r & 127;
    const int byte = 2 * c;                   // multiple of 16
    const unsigned off = (unsigned)(byte >> 6) * TILE32
                       + SWB32(lr, (byte & 63) >> 4);
    *(uint4*)((char*)outH + base + off) = *(uint4*)h;
    *(uint4*)((char*)outL + base + off) = *(uint4*)l;
}

// ---------------------------------------------------------------------------
// FMA-pipe exp for x <= 0 (MUFU EX2 is quarter-rate on B300).
// ---------------------------------------------------------------------------
__device__ __forceinline__ float fexp(float x) {
    float y = x * 1.4426950408889634f;
    float n = floorf(y);
    float f = y - n;
    float p = 0.000154035304f;
    p = fmaf(p, f, 0.00133335581f);
    p = fmaf(p, f, 0.00961812910f);
    p = fmaf(p, f, 0.0555041087f);
    p = fmaf(p, f, 0.240226507f);
    p = fmaf(p, f, 0.693147180f);
    p = fmaf(p, f, 1.0f);
    int ni = (int)n;
    if (ni < -126) return 0.f;
    return p * __int_as_float((ni + 127) << 23);
}

// ---------------------------------------------------------------------------
// causal softmax: fp32 scores -> (h,l) att planes (tiled, tile-bounded writes)
// ---------------------------------------------------------------------------
__global__ void softmax_split_kernel(const float* __restrict__ att,
                                     __nv_bfloat16* __restrict__ attH,
                                     __nv_bfloat16* __restrict__ attL, int Tn)
{
    __shared__ float buf[2048];
    __shared__ float red[256];
    const int row = blockIdx.x;
    const int t = row % Tn;
    const float* p = att + (long long)row * Tn;
    const int tid = threadIdx.x;
    const int len = t + 1;
    const int lenR = (t & ~255) + 256;        // 256-row GEMM tile boundary

    float m = -1e30f;
    for (int s = tid; s < len; s += 256) { float v = p[s]; buf[s] = v; m = fmaxf(m, v); }
    red[tid] = m; __syncthreads();
    for (int off = 128; off > 0; off >>= 1) {
        if (tid < off) red[tid] = fmaxf(red[tid], red[tid + off]);
        __syncthreads();
    }
    m = red[0]; __syncthreads();

    float sum = 0.f;
    for (int s = tid; s < len; s += 256) {
        float e = fexp(buf[s] - m);
        buf[s] = e;
        sum += e;
    }
    red[tid] = sum; __syncthreads();
    for (int off = 128; off > 0; off >>= 1) {
        if (tid < off) red[tid] += red[tid + off];
        __syncthreads();
    }
    const float inv = 1.f / red[0];
    __syncthreads();

    const int s8 = tid * 8;                   // 8 tokens per thread
    if (s8 < lenR) {
        alignas(16) unsigned short h[8], l[8];
        #pragma unroll
        for (int j = 0; j < 8; j++) {
            const int s = s8 + j;
            const float e = (s < len) ? buf[s] * inv : 0.f;
            split2(e, h[j], l[j]);
        }
        const size_t base = (size_t)(row >> 7) * 64 * TILE32;
        const int lr = row & 127;
        const int byte = 2 * s8;
        const unsigned off = (unsigned)(byte >> 6) * TILE32
                           + SWB32(lr, (byte & 63) >> 4);
        *(uint4*)((char*)attH + base + off) = *(uint4*)h;
        *(uint4*)((char*)attL + base + off) = *(uint4*)l;
    }
}

// ---------------------------------------------------------------------------
extern "C" void kernel_launch(void* const* d_in, const int* in_sizes, int n_in,
                              void* d_out, int out_size)
{
    const float* x      = (const float*)d_in[0];
    const float* w_qkv  = (const float*)d_in[1];
    const float* b_qkv  = (const float*)d_in[2];
    const float* w_proj = (const float*)d_in[3];
    const float* b_proj = (const float*)d_in[4];
    float* out = (float*)d_out;

    float *att;
    __nv_bfloat16 *xH, *xL, *wqH, *wqL, *wpH, *wpL;
    __nv_bfloat16 *qH, *qL, *kH, *kL, *vH, *vL, *vwH, *vwL, *aH, *aL;
    cudaGetSymbolAddress((void**)&att, g_att);
    cudaGetSymbolAddress((void**)&xH,  g_xH);  cudaGetSymbolAddress((void**)&xL,  g_xL);
    cudaGetSymbolAddress((void**)&wqH, g_wqH); cudaGetSymbolAddress((void**)&wqL, g_wqL);
    cudaGetSymbolAddress((void**)&wpH, g_wpH); cudaGetSymbolAddress((void**)&wpL, g_wpL);
    cudaGetSymbolAddress((void**)&qH,  g_qH);  cudaGetSymbolAddress((void**)&qL,  g_qL);
    cudaGetSymbolAddress((void**)&kH,  g_kH);  cudaGetSymbolAddress((void**)&kL,  g_kL);
    cudaGetSymbolAddress((void**)&vH,  g_vH);  cudaGetSymbolAddress((void**)&vL,  g_vL);
    cudaGetSymbolAddress((void**)&vwH, g_vwH); cudaGetSymbolAddress((void**)&vwL, g_vwL);
    cudaGetSymbolAddress((void**)&aH,  g_aH);  cudaGetSymbolAddress((void**)&aL,  g_aL);

    cudaFuncSetAttribute(hmma_gemm,
        cudaFuncAttributeMaxDynamicSharedMemorySize, GEMM_SMEM);

    const float inv_sqrt_c = 0.03125f;

    // split the raw inputs into (h,l) planes
    split2_kernel<<<(M * (C / 8) + 255) / 256, 256>>>(x, xH, xL, M, C, C);
    split2_kernel<<<(3 * C * (C / 8) + 255) / 256, 256>>>(w_qkv, wqH, wqL, 3 * C, C, C);
    split2_kernel<<<(C * (C / 8) + 255) / 256, 256>>>(w_proj, wpH, wpL, C, C, C);

    // 1) qkv GEMM -> q / k / v planes
    hmma_gemm<<<dim3(3 * C / 128, M / 256, 1), 256, GEMM_SMEM>>>(
        (const char*)xH, (const char*)xL, (const char*)wqH, (const char*)wqL,
        nullptr, (char*)qH, (char*)qL, (char*)kH, (char*)kL, (char*)vH, (char*)vL,
        32, 32, 0, 32, 0, 0, 0,
        1.f, b_qkv, 0, 0, C, 2);

    // 2) VWt[c,s] = Wp @ V^T per batch -> vw planes [c rows, s chunks]
    hmma_gemm<<<dim3(T / 128, C / 256, Bb), 256, GEMM_SMEM>>>(
        (const char*)wpH, (const char*)wpL, (const char*)vH, (const char*)vL,
        nullptr, (char*)vwH, (char*)vwL, nullptr, nullptr, nullptr, nullptr,
        32, 32, 0, 64,
        0, 16 * 32, 8 * 64,
        1.f, nullptr, 0, 0, C, 1);

    // 3) scores = (q @ k^T) / sqrt(C), causal tile-skip, fp32 out
    hmma_gemm<<<dim3(T / 128, T / 256, Bb), 256, GEMM_SMEM>>>(
        (const char*)qH, (const char*)qL, (const char*)kH, (const char*)kL,
        att, nullptr, nullptr, nullptr, nullptr, nullptr, nullptr,
        32, 32, T, 0,
        16 * 32, 16 * 32, (long long)T * T,
        inv_sqrt_c, nullptr, 1, 0, C, 0);

    // 4) softmax -> att planes (tile-bounded writes)
    softmax_split_kernel<<<M, 256>>>(att, aH, aL, T);

    // 5) out = att @ VWt^T + b_proj  (k-limited by causality, fp32 out)
    hmma_gemm<<<dim3(C / 128, T / 256, Bb), 256, GEMM_SMEM>>>(
        (const char*)aH, (const char*)aL, (const char*)vwH, (const char*)vwL,
        out, nullptr, nullptr, nullptr, nullptr, nullptr, nullptr,
        64, 64, C, 0,
        16 * 64, 8 * 64, (long long)T * C,
        1.f, b_proj, 0, 1, T, 0);
}

// round 15
// speedup vs baseline: 1.0995x; 1.0995x over previous
#include <cuda_runtime.h>
#include <cuda_bf16.h>
#include <math.h>

// ---------------------------------------------------------------------------
// Causal self-attention block via mma.sync (HMMA bf16) on sm_103.
// fp32 emulation by SEGMENTED 2-plane bf16 split (H,L over original K);
// GEMM computes AhBh + AlBh + AhBl (drops only AlBl ~2^-18).
// R15: revert to R12 GEMM (best measured). NEW: scores and vw GEMMs are
// independent -> merged into ONE launch (blockIdx.y dispatch) so vw fills
// scores' causal-skip bubbles. Input splits fused into one kernel.
// ---------------------------------------------------------------------------

static const int Bb = 4, T = 2048, C = 1024;
static const int M = Bb * T;          // 8192

#define TILE32 8192                   // 128 rows x 32 k x 2B

// fp32 intermediates
__device__ float g_att[(size_t)4 * 2048 * 2048];
// (H,L) bf16 planes, tiled [row_stripe][chunk][8KB swizzled]
__device__ __nv_bfloat16 g_xH [(size_t)8192 * 1024];
__device__ __nv_bfloat16 g_xL [(size_t)8192 * 1024];
__device__ __nv_bfloat16 g_wqH[(size_t)3072 * 1024];
__device__ __nv_bfloat16 g_wqL[(size_t)3072 * 1024];
__device__ __nv_bfloat16 g_wpH[(size_t)1024 * 1024];
__device__ __nv_bfloat16 g_wpL[(size_t)1024 * 1024];
__device__ __nv_bfloat16 g_qH [(size_t)8192 * 1024];
__device__ __nv_bfloat16 g_qL [(size_t)8192 * 1024];
__device__ __nv_bfloat16 g_kH [(size_t)8192 * 1024];
__device__ __nv_bfloat16 g_kL [(size_t)8192 * 1024];
__device__ __nv_bfloat16 g_vH [(size_t)8192 * 1024];
__device__ __nv_bfloat16 g_vL [(size_t)8192 * 1024];
__device__ __nv_bfloat16 g_vwH[(size_t)4 * 1024 * 2048];
__device__ __nv_bfloat16 g_vwL[(size_t)4 * 1024 * 2048];
__device__ __nv_bfloat16 g_aH [(size_t)8192 * 2048];
__device__ __nv_bfloat16 g_aL [(size_t)8192 * 2048];

// swizzle for 64-byte rows (32 bf16): 16B slot c (0..3) -> c ^ ((r>>1)&3)
#define SWB32(r, c) ((unsigned)((r) * 64 + ((((c) ^ (((r) >> 1) & 3)) & 3) << 4)))

__device__ __forceinline__ void ldm4(unsigned* r, unsigned addr) {
    asm volatile("ldmatrix.sync.aligned.m8n8.x4.shared.b16 {%0,%1,%2,%3}, [%4];"
        : "=r"(r[0]), "=r"(r[1]), "=r"(r[2]), "=r"(r[3]) : "r"(addr));
}
__device__ __forceinline__ void mma16816(float* d, const unsigned* a,
                                         unsigned b0, unsigned b1) {
    asm volatile(
        "mma.sync.aligned.m16n8k16.row.col.f32.bf16.bf16.f32 "
        "{%0,%1,%2,%3}, {%4,%5,%6,%7}, {%8,%9}, {%0,%1,%2,%3};"
        : "+f"(d[0]), "+f"(d[1]), "+f"(d[2]), "+f"(d[3])
        : "r"(a[0]), "r"(a[1]), "r"(a[2]), "r"(a[3]), "r"(b0), "r"(b1));
}
__device__ __forceinline__ void bulk8k(unsigned sdst, const void* g, unsigned mb) {
    unsigned sz = TILE32;
    asm volatile(
        "cp.async.bulk.shared::cluster.global.mbarrier::complete_tx::bytes "
        "[%0], [%1], %2, [%3];"
        :: "r"(sdst), "l"(__cvta_generic_to_global(g)), "r"(sz), "r"(mb)
        : "memory");
}
__device__ __forceinline__ void mbar_wait(unsigned mbar, unsigned parity) {
    asm volatile(
        "{\n\t.reg .pred P;\n\t"
        "LW_%=:\n\t"
        "mbarrier.try_wait.parity.acquire.cta.shared::cta.b64 P, [%0], %1, 0x989680;\n\t"
        "@P bra.uni LD_%=;\n\t"
        "bra.uni LW_%=;\n\t"
        "LD_%=:\n\t}"
        :: "r"(mbar), "r"(parity) : "memory");
}
__device__ __forceinline__ void mbar_arrive(unsigned mbar) {
    asm volatile("mbarrier.arrive.release.cta.shared.b64 _, [%0];"
                 :: "r"(mbar) : "memory");
}

__device__ __forceinline__ void split2(float v, unsigned short& h, unsigned short& l) {
    __nv_bfloat16 hb = __float2bfloat16(v);
    __nv_bfloat16 lb = __float2bfloat16(v - __bfloat162float(hb));
    h = __bfloat16_as_ushort(hb);
    l = __bfloat16_as_ushort(lb);
}

#define STAGE_BYTES 32768 // Ah 8K + Al 8K + Bh 8K + Bl 8K
#define NSTG 3
#define GEMM_SMEM (NSTG * STAGE_BYTES + 128)

// ---------------------------------------------------------------------------
// GEMM body (R12 structure): 128 threads, 4 warps, 64x64 warp tiles over a
// 128x128 CTA tile; 3-stage bulk pipeline, product-granularity LDSM.
// emode 0: fp32 out; 1: plane out D1; 2: qkv triple D1/D2/D3.
// ---------------------------------------------------------------------------
__device__ __forceinline__ void gemm_body(
    const char* AH, const char* AL, const char* BH, const char* BL,
    float* Cf, char* D1H, char* D1L, char* D2H, char* D2L,
    char* D3H, char* D3L,
    int ncha, int nchb, int ldcf, int nchc,
    long long sAt, long long sBt, long long sC,
    float alpha, const float* bias,
    int causal_skip, int klimit, int K, int emode,
    int row0, int col0, int bz)
{
    if (causal_skip && col0 > row0) return;              // strictly-upper tiles
    const int kend = klimit ? min(K, row0 + 128) : K;
    const int nch = kend >> 5;                           // 32-k chunks

    const long long aoff = ((long long)bz * sAt + (row0 >> 7) * ncha) * TILE32;
    const long long boff = ((long long)bz * sBt + (col0 >> 7) * nchb) * TILE32;
    AH += aoff; AL += aoff; BH += boff; BL += boff;

    extern __shared__ __align__(128) unsigned char smem[];
    const unsigned sb = (unsigned)__cvta_generic_to_shared(smem);
    const unsigned mbF = sb + NSTG * STAGE_BYTES;        // full barriers
    const unsigned mbE = mbF + 8 * NSTG;                 // empty barriers

    const int tid = threadIdx.x;
    const int lane = tid & 31;
    const int wid = tid >> 5;          // 0..3
    const int wm = wid >> 1;           // 0..1 -> 64-row half
    const int wn = wid & 1;            // 0..1 -> 64-col half

    if (tid == 0) {
        #pragma unroll
        for (int s = 0; s < NSTG; s++) {
            asm volatile("mbarrier.init.shared.b64 [%0], 1;"
                         :: "r"(mbF + 8 * s) : "memory");
            asm volatile("mbarrier.init.shared.b64 [%0], 128;"
                         :: "r"(mbE + 8 * s) : "memory");
        }
    }
    __syncthreads();

    float acc[4][8][4];
    #pragma unroll
    for (int i = 0; i < 4; i++)
        #pragma unroll
        for (int j = 0; j < 8; j++)
            #pragma unroll
            for (int k = 0; k < 4; k++) acc[i][j][k] = 0.f;

    auto bulk_load = [&](int chunk) {      // tid0 only
        const int st = chunk % NSTG;
        if (chunk >= NSTG)
            mbar_wait(mbE + 8 * st, (chunk / NSTG - 1) & 1);
        const unsigned mb = mbF + 8 * st;
        asm volatile("mbarrier.arrive.expect_tx.shared.b64 _, [%0], %1;"
                     :: "r"(mb), "r"((unsigned)STAGE_BYTES) : "memory");
        const unsigned s0 = sb + st * STAGE_BYTES;
        const size_t co = (size_t)chunk * TILE32;
        bulk8k(s0,          AH + co, mb);
        bulk8k(s0 + 8192,   AL + co, mb);
        bulk8k(s0 + 16384,  BH + co, mb);
        bulk8k(s0 + 24576,  BL + co, mb);
    };

    const int sfirst = wid & 1;       // warp-parity slice stagger
    auto compute = [&](int chunk) {
        const int st = chunk % NSTG;
        const unsigned s0 = sb + st * STAGE_BYTES;
        mbar_wait(mbF + 8 * st, (chunk / NSTG) & 1);
        #pragma unroll
        for (int si = 0; si < 2; si++) {
            const int s = si ^ sfirst;
            const int ch = 2 * s + (lane >> 4);
            unsigned AhF[4][4], AlF[4][4], BhF[4][4], BlF[4][4];
            #pragma unroll
            for (int mb = 0; mb < 4; mb++) {
                const int mr = wm * 64 + mb * 16 + (lane & 15);
                ldm4(AhF[mb], s0 + SWB32(mr, ch));
            }
            #pragma unroll
            for (int nb = 0; nb < 4; nb++) {
                const int nr = wn * 64 + nb * 16 + (lane & 15);
                ldm4(BhF[nb], s0 + 16384 + SWB32(nr, ch));
            }
            #pragma unroll
            for (int mb = 0; mb < 4; mb++)
                #pragma unroll
                for (int nb = 0; nb < 4; nb++) {
                    mma16816(acc[mb][nb * 2 + 0], AhF[mb], BhF[nb][0], BhF[nb][2]);
                    mma16816(acc[mb][nb * 2 + 1], AhF[mb], BhF[nb][1], BhF[nb][3]);
                }
            #pragma unroll
            for (int mb = 0; mb < 4; mb++) {
                const int mr = wm * 64 + mb * 16 + (lane & 15);
                ldm4(AlF[mb], s0 + 8192 + SWB32(mr, ch));
            }
            #pragma unroll
            for (int mb = 0; mb < 4; mb++)
                #pragma unroll
                for (int nb = 0; nb < 4; nb++) {
                    mma16816(acc[mb][nb * 2 + 0], AlF[mb], BhF[nb][0], BhF[nb][2]);
                    mma16816(acc[mb][nb * 2 + 1], AlF[mb], BhF[nb][1], BhF[nb][3]);
                }
            #pragma unroll
            for (int nb = 0; nb < 4; nb++) {
                const int nr = wn * 64 + nb * 16 + (lane & 15);
                ldm4(BlF[nb], s0 + 24576 + SWB32(nr, ch));
            }
            if (si == 1)                   // last smem read of this stage
                mbar_arrive(mbE + 8 * st);
            #pragma unroll
            for (int mb = 0; mb < 4; mb++)
                #pragma unroll
                for (int nb = 0; nb < 4; nb++) {
                    mma16816(acc[mb][nb * 2 + 0], AhF[mb], BlF[nb][0], BlF[nb][2]);
                    mma16816(acc[mb][nb * 2 + 1], AhF[mb], BlF[nb][1], BlF[nb][3]);
                }
        }
    };

    if (tid == 0) {
        bulk_load(0);
        if (nch > 1) bulk_load(1);
    }
    for (int i = 0; i < nch; i++) {
        if (tid == 0 && i + 2 < nch) bulk_load(i + 2);
        compute(i);
    }

    // ----- epilogue -----
    char *dH = 0, *dL = 0;
    int colr = col0;
    float* df = 0;
    long long ztile = 0;
    if (emode == 0) {
        df = Cf + (long long)bz * sC;
    } else if (emode == 1) {
        dH = D1H; dL = D1L; ztile = (long long)bz * sC;   // sC in tiles
    } else {                                  // qkv triple
        if (col0 < 1024)      { dH = D1H; dL = D1L; colr = col0; }
        else if (col0 < 2048) { dH = D2H; dL = D2L; colr = col0 - 1024; }
        else                  { dH = D3H; dL = D3L; colr = col0 - 2048; }
    }

    const int cbase = wn * 64 + 2 * (lane & 3);
    #pragma unroll
    for (int mb = 0; mb < 4; mb++) {
        #pragma unroll
        for (int half = 0; half < 2; half++) {
            const int r = row0 + wm * 64 + mb * 16 + (lane >> 2) + half * 8;
            const long long tb = dH ? (ztile + (long long)(r >> 7) * nchc) * TILE32 : 0;
            const int lr = r & 127;
            #pragma unroll
            for (int nb = 0; nb < 8; nb++) {
                const int cr = colr + cbase + nb * 8;    // region-relative (even)
                const int ca = col0 + cbase + nb * 8;    // absolute (bias)
                float vx = acc[mb][nb][half * 2 + 0] * alpha;
                float vy = acc[mb][nb][half * 2 + 1] * alpha;
                if (bias) { vx += bias[ca]; vy += bias[ca + 1]; }
                if (dH) {
                    unsigned short hx, lx, hy, ly;
                    split2(vx, hx, lx);
                    split2(vy, hy, ly);
                    const int byte = 2 * cr;             // multiple of 4
                    const unsigned off = (unsigned)(byte >> 6) * TILE32
                                       + SWB32(lr, (byte & 63) >> 4) + (byte & 15);
                    *(unsigned*)(dH + tb + off) = (unsigned)hx | ((unsigned)hy << 16);
                    *(unsigned*)(dL + tb + off) = (unsigned)lx | ((unsigned)ly << 16);
                } else {
                    *(float2*)(df + (long long)r * ldcf + cr) = make_float2(vx, vy);
                }
            }
        }
    }
}

// generic wrapper
__global__ void __launch_bounds__(128, 2)
hmma_gemm(const char* __restrict__ AH, const char* __restrict__ AL,
          const char* __restrict__ BH, const char* __restrict__ BL,
          float* __restrict__ Cf,
          char* __restrict__ D1H, char* __restrict__ D1L,
          char* __restrict__ D2H, char* __restrict__ D2L,
          char* __restrict__ D3H, char* __restrict__ D3L,
          int ncha, int nchb, int ldcf, int nchc,
          long long sAt, long long sBt, long long sC,
          float alpha, const float* __restrict__ bias,
          int causal_skip, int klimit, int K, int emode)
{
    gemm_body(AH, AL, BH, BL, Cf, D1H, D1L, D2H, D2L, D3H, D3L,
              ncha, nchb, ldcf, nchc, sAt, sBt, sC, alpha, bias,
              causal_skip, klimit, K, emode,
              blockIdx.y * 128, blockIdx.x * 128, blockIdx.z);
}

// fused scores + vw: grid (16, 16+8, 4). y<16 -> scores tile; y>=16 -> vw.
// Params phi-selected before one call site (single inlined body).
__global__ void __launch_bounds__(128, 2)
fused_scores_vw()
{
    const char *AH, *AL, *BH, *BL;
    float* Cf = 0;
    char *D1H = 0, *D1L = 0;
    int ncha, nchb, ldcf, nchc, causal_skip, emode, row0;
    long long sAt, sBt, sC;
    float alpha;
    if (blockIdx.y < 16) {          // scores = q @ k^T / sqrt(C)
        AH = (const char*)g_qH;  AL = (const char*)g_qL;
        BH = (const char*)g_kH;  BL = (const char*)g_kL;
        Cf = g_att;
        ncha = 32; nchb = 32; ldcf = 2048; nchc = 0;
        sAt = 16 * 32; sBt = 16 * 32; sC = (long long)2048 * 2048;
        alpha = 0.03125f; causal_skip = 1; emode = 0;
        row0 = blockIdx.y * 128;
    } else {                        // vw = Wp @ V^T
        AH = (const char*)g_wpH; AL = (const char*)g_wpL;
        BH = (const char*)g_vH;  BL = (const char*)g_vL;
        D1H = (char*)g_vwH; D1L = (char*)g_vwL;
        ncha = 32; nchb = 32; ldcf = 0; nchc = 64;
        sAt = 0; sBt = 16 * 32; sC = 8 * 64;
        alpha = 1.f; causal_skip = 0; emode = 1;
        row0 = (blockIdx.y - 16) * 128;
    }
    gemm_body(AH, AL, BH, BL, Cf, D1H, D1L, 0, 0, 0, 0,
              ncha, nchb, ldcf, nchc, sAt, sBt, sC, alpha, nullptr,
              causal_skip, 0, 1024, emode,
              row0, blockIdx.x * 128, blockIdx.z);
}

// ---------------------------------------------------------------------------
// fused input splits: rows [0,8192) = x, [8192,11264) = w_qkv,
// [11264,12288) = w_proj. All Cin=1024, ld=1024.
// ---------------------------------------------------------------------------
__global__ void split_inputs_kernel(const float* __restrict__ x,
                                    const float* __restrict__ wq,
                                    const float* __restrict__ wp)
{
    long long idx = (long long)blockIdx.x * blockDim.x + threadIdx.x;
    if (idx >= (long long)12288 * 128) return;
    int r = (int)(idx >> 7);
    const int c = (int)(idx & 127) * 8;

    const float* in;
    __nv_bfloat16 *outH, *outL;
    if (r < 8192)       { in = x;  outH = g_xH;  outL = g_xL; }
    else if (r < 11264) { in = wq; outH = g_wqH; outL = g_wqL; r -= 8192; }
    else                { in = wp; outH = g_wpH; outL = g_wpL; r -= 11264; }

    const float4 v0 = *(const float4*)(in + (long long)r * 1024 + c);
    const float4 v1 = *(const float4*)(in + (long long)r * 1024 + c + 4);
    float f[8] = {v0.x, v0.y, v0.z, v0.w, v1.x, v1.y, v1.z, v1.w};

    alignas(16) unsigned short h[8], l[8];
    #pragma unroll
    for (int j = 0; j < 8; j++) split2(f[j], h[j], l[j]);

    const size_t base = (size_t)(r >> 7) * 32 * TILE32;
    const int lr = r & 127;
    const int byte = 2 * c;                   // multiple of 16
    const unsigned off = (unsigned)(byte >> 6) * TILE32
                       + SWB32(lr, (byte & 63) >> 4);
    *(uint4*)((char*)outH + base + off) = *(uint4*)h;
    *(uint4*)((char*)outL + base + off) = *(uint4*)l;
}

// ---------------------------------------------------------------------------
// FMA-pipe exp for x <= 0 (MUFU EX2 is quarter-rate on B300).
// ---------------------------------------------------------------------------
__device__ __forceinline__ float fexp(float x) {
    float y = x * 1.4426950408889634f;
    float n = floorf(y);
    float f = y - n;
    float p = 0.000154035304f;
    p = fmaf(p, f, 0.00133335581f);
    p = fmaf(p, f, 0.00961812910f);
    p = fmaf(p, f, 0.0555041087f);
    p = fmaf(p, f, 0.240226507f);
    p = fmaf(p, f, 0.693147180f);
    p = fmaf(p, f, 1.0f);
    int ni = (int)n;
    if (ni < -126) return 0.f;
    return p * __int_as_float((ni + 127) << 23);
}

// ---------------------------------------------------------------------------
// causal softmax: fp32 scores -> (h,l) att planes (tiled, tile-bounded writes)
// ---------------------------------------------------------------------------
__global__ void softmax_split_kernel(const float* __restrict__ att,
                                     __nv_bfloat16* __restrict__ attH,
                                     __nv_bfloat16* __restrict__ attL, int Tn)
{
    __shared__ float buf[2048];
    __shared__ float red[256];
    const int row = blockIdx.x;
    const int t = row % Tn;
    const float* p = att + (long long)row * Tn;
    const int tid = threadIdx.x;
    const int len = t + 1;
    const int lenR = (t & ~127) + 128;        // = row-tile boundary

    float m = -1e30f;
    for (int s = tid; s < len; s += 256) { float v = p[s]; buf[s] = v; m = fmaxf(m, v); }
    red[tid] = m; __syncthreads();
    for (int off = 128; off > 0; off >>= 1) {
        if (tid < off) red[tid] = fmaxf(red[tid], red[tid + off]);
        __syncthreads();
    }
    m = red[0]; __syncthreads();

    float sum = 0.f;
    for (int s = tid; s < len; s += 256) {
        float e = fexp(buf[s] - m);
        buf[s] = e;
        sum += e;
    }
    red[tid] = sum; __syncthreads();
    for (int off = 128; off > 0; off >>= 1) {
        if (tid < off) red[tid] += red[tid + off];
        __syncthreads();
    }
    const float inv = 1.f / red[0];
    __syncthreads();

    const int s8 = tid * 8;                   // 8 tokens per thread
    if (s8 < lenR) {
        alignas(16) unsigned short h[8], l[8];
        #pragma unroll
        for (int j = 0; j < 8; j++) {
            const int s = s8 + j;
            const float e = (s < len) ? buf[s] * inv : 0.f;
            split2(e, h[j], l[j]);
        }
        const size_t base = (size_t)(row >> 7) * 64 * TILE32;
        const int lr = row & 127;
        const int byte = 2 * s8;
        const unsigned off = (unsigned)(byte >> 6) * TILE32
                           + SWB32(lr, (byte & 63) >> 4);
        *(uint4*)((char*)attH + base + off) = *(uint4*)h;
        *(uint4*)((char*)attL + base + off) = *(uint4*)l;
    }
}

// ---------------------------------------------------------------------------
extern "C" void kernel_launch(void* const* d_in, const int* in_sizes, int n_in,
                              void* d_out, int out_size)
{
    const float* x      = (const float*)d_in[0];
    const float* w_qkv  = (const float*)d_in[1];
    const float* b_qkv  = (const float*)d_in[2];
    const float* w_proj = (const float*)d_in[3];
    const float* b_proj = (const float*)d_in[4];
    float* out = (float*)d_out;

    float *att;
    __nv_bfloat16 *xH, *xL, *wqH, *wqL;
    __nv_bfloat16 *qH, *qL, *kH, *kL, *vH, *vL, *vwH, *vwL, *aH, *aL;
    cudaGetSymbolAddress((void**)&att, g_att);
    cudaGetSymbolAddress((void**)&xH,  g_xH);  cudaGetSymbolAddress((void**)&xL,  g_xL);
    cudaGetSymbolAddress((void**)&wqH, g_wqH); cudaGetSymbolAddress((void**)&wqL, g_wqL);
    cudaGetSymbolAddress((void**)&qH,  g_qH);  cudaGetSymbolAddress((void**)&qL,  g_qL);
    cudaGetSymbolAddress((void**)&kH,  g_kH);  cudaGetSymbolAddress((void**)&kL,  g_kL);
    cudaGetSymbolAddress((void**)&vH,  g_vH);  cudaGetSymbolAddress((void**)&vL,  g_vL);
    cudaGetSymbolAddress((void**)&vwH, g_vwH); cudaGetSymbolAddress((void**)&vwL, g_vwL);
    cudaGetSymbolAddress((void**)&aH,  g_aH);  cudaGetSymbolAddress((void**)&aL,  g_aL);

    cudaFuncSetAttribute(hmma_gemm,
        cudaFuncAttributeMaxDynamicSharedMemorySize, GEMM_SMEM);
    cudaFuncSetAttribute(fused_scores_vw,
        cudaFuncAttributeMaxDynamicSharedMemorySize, GEMM_SMEM);

    // 0) fused input splits (x, w_qkv, w_proj)
    split_inputs_kernel<<<(12288 * 128 + 255) / 256, 256>>>(x, w_qkv, w_proj);

    // 1) qkv GEMM -> q / k / v planes
    hmma_gemm<<<dim3(3 * C / 128, M / 128, 1), 128, GEMM_SMEM>>>(
        (const char*)xH, (const char*)xL, (const char*)wqH, (const char*)wqL,
        nullptr, (char*)qH, (char*)qL, (char*)kH, (char*)kL, (char*)vH, (char*)vL,
        32, 32, 0, 32, 0, 0, 0,
        1.f, b_qkv, 0, 0, C, 2);

    // 2+3) FUSED: scores (causal, fp32 att) + vw = Wp @ V^T (plane out)
    fused_scores_vw<<<dim3(T / 128, T / 128 + C / 128, Bb), 128, GEMM_SMEM>>>();

    // 4) softmax -> att planes (tile-bounded writes)
    softmax_split_kernel<<<M, 256>>>(att, aH, aL, T);

    // 5) out = att @ VWt^T + b_proj  (k-limited by causality, fp32 out)
    hmma_gemm<<<dim3(C / 128, T / 128, Bb), 128, GEMM_SMEM>>>(
        (const char*)aH, (const char*)aL, (const char*)vwH, (const char*)vwL,
        out, nullptr, nullptr, nullptr, nullptr, nullptr, nullptr,
        64, 64, C, 0,
        16 * 64, 8 * 64, (long long)T * C,
        1.f, b_proj, 0, 1, T, 0);
}

// round 16
// speedup vs baseline: 1.1386x; 1.0355x over previous
#include <cuda_runtime.h>
#include <cuda_bf16.h>
#include <math.h>

// ---------------------------------------------------------------------------
// Causal self-attention block via mma.sync (HMMA bf16) on sm_103.
// fp32 emulation by SEGMENTED 2-plane bf16 split (H,L over original K);
// GEMM computes AhBh + AlBh + AhBl (drops only AlBl ~2^-18).
// R16: att@VW launch runs longest-row-tiles FIRST (descending k-limit) to
// fix triangular wave imbalance; softmax reductions via warp shuffles.
// ---------------------------------------------------------------------------

static const int Bb = 4, T = 2048, C = 1024;
static const int M = Bb * T;          // 8192

#define TILE32 8192                   // 128 rows x 32 k x 2B

// fp32 intermediates
__device__ float g_att[(size_t)4 * 2048 * 2048];
// (H,L) bf16 planes, tiled [row_stripe][chunk][8KB swizzled]
__device__ __nv_bfloat16 g_xH [(size_t)8192 * 1024];
__device__ __nv_bfloat16 g_xL [(size_t)8192 * 1024];
__device__ __nv_bfloat16 g_wqH[(size_t)3072 * 1024];
__device__ __nv_bfloat16 g_wqL[(size_t)3072 * 1024];
__device__ __nv_bfloat16 g_wpH[(size_t)1024 * 1024];
__device__ __nv_bfloat16 g_wpL[(size_t)1024 * 1024];
__device__ __nv_bfloat16 g_qH [(size_t)8192 * 1024];
__device__ __nv_bfloat16 g_qL [(size_t)8192 * 1024];
__device__ __nv_bfloat16 g_kH [(size_t)8192 * 1024];
__device__ __nv_bfloat16 g_kL [(size_t)8192 * 1024];
__device__ __nv_bfloat16 g_vH [(size_t)8192 * 1024];
__device__ __nv_bfloat16 g_vL [(size_t)8192 * 1024];
__device__ __nv_bfloat16 g_vwH[(size_t)4 * 1024 * 2048];
__device__ __nv_bfloat16 g_vwL[(size_t)4 * 1024 * 2048];
__device__ __nv_bfloat16 g_aH [(size_t)8192 * 2048];
__device__ __nv_bfloat16 g_aL [(size_t)8192 * 2048];

// swizzle for 64-byte rows (32 bf16): 16B slot c (0..3) -> c ^ ((r>>1)&3)
#define SWB32(r, c) ((unsigned)((r) * 64 + ((((c) ^ (((r) >> 1) & 3)) & 3) << 4)))

__device__ __forceinline__ void ldm4(unsigned* r, unsigned addr) {
    asm volatile("ldmatrix.sync.aligned.m8n8.x4.shared.b16 {%0,%1,%2,%3}, [%4];"
        : "=r"(r[0]), "=r"(r[1]), "=r"(r[2]), "=r"(r[3]) : "r"(addr));
}
__device__ __forceinline__ void mma16816(float* d, const unsigned* a,
                                         unsigned b0, unsigned b1) {
    asm volatile(
        "mma.sync.aligned.m16n8k16.row.col.f32.bf16.bf16.f32 "
        "{%0,%1,%2,%3}, {%4,%5,%6,%7}, {%8,%9}, {%0,%1,%2,%3};"
        : "+f"(d[0]), "+f"(d[1]), "+f"(d[2]), "+f"(d[3])
        : "r"(a[0]), "r"(a[1]), "r"(a[2]), "r"(a[3]), "r"(b0), "r"(b1));
}
__device__ __forceinline__ void bulk8k(unsigned sdst, const void* g, unsigned mb) {
    unsigned sz = TILE32;
    asm volatile(
        "cp.async.bulk.shared::cluster.global.mbarrier::complete_tx::bytes "
        "[%0], [%1], %2, [%3];"
        :: "r"(sdst), "l"(__cvta_generic_to_global(g)), "r"(sz), "r"(mb)
        : "memory");
}
__device__ __forceinline__ void mbar_wait(unsigned mbar, unsigned parity) {
    asm volatile(
        "{\n\t.reg .pred P;\n\t"
        "LW_%=:\n\t"
        "mbarrier.try_wait.parity.acquire.cta.shared::cta.b64 P, [%0], %1, 0x989680;\n\t"
        "@P bra.uni LD_%=;\n\t"
        "bra.uni LW_%=;\n\t"
        "LD_%=:\n\t}"
        :: "r"(mbar), "r"(parity) : "memory");
}
__device__ __forceinline__ void mbar_arrive(unsigned mbar) {
    asm volatile("mbarrier.arrive.release.cta.shared.b64 _, [%0];"
                 :: "r"(mbar) : "memory");
}

__device__ __forceinline__ void split2(float v, unsigned short& h, unsigned short& l) {
    __nv_bfloat16 hb = __float2bfloat16(v);
    __nv_bfloat16 lb = __float2bfloat16(v - __bfloat162float(hb));
    h = __bfloat16_as_ushort(hb);
    l = __bfloat16_as_ushort(lb);
}

#define STAGE_BYTES 32768 // Ah 8K + Al 8K + Bh 8K + Bl 8K
#define NSTG 3
#define GEMM_SMEM (NSTG * STAGE_BYTES + 128)

// ---------------------------------------------------------------------------
// GEMM body (R12 structure): 128 threads, 4 warps, 64x64 warp tiles over a
// 128x128 CTA tile; 3-stage bulk pipeline, product-granularity LDSM.
// emode 0: fp32 out; 1: plane out D1; 2: qkv triple D1/D2/D3.
// ---------------------------------------------------------------------------
__device__ __forceinline__ void gemm_body(
    const char* AH, const char* AL, const char* BH, const char* BL,
    float* Cf, char* D1H, char* D1L, char* D2H, char* D2L,
    char* D3H, char* D3L,
    int ncha, int nchb, int ldcf, int nchc,
    long long sAt, long long sBt, long long sC,
    float alpha, const float* bias,
    int causal_skip, int klimit, int K, int emode,
    int row0, int col0, int bz)
{
    if (causal_skip && col0 > row0) return;              // strictly-upper tiles
    const int kend = klimit ? min(K, row0 + 128) : K;
    const int nch = kend >> 5;                           // 32-k chunks

    const long long aoff = ((long long)bz * sAt + (row0 >> 7) * ncha) * TILE32;
    const long long boff = ((long long)bz * sBt + (col0 >> 7) * nchb) * TILE32;
    AH += aoff; AL += aoff; BH += boff; BL += boff;

    extern __shared__ __align__(128) unsigned char smem[];
    const unsigned sb = (unsigned)__cvta_generic_to_shared(smem);
    const unsigned mbF = sb + NSTG * STAGE_BYTES;        // full barriers
    const unsigned mbE = mbF + 8 * NSTG;                 // empty barriers

    const int tid = threadIdx.x;
    const int lane = tid & 31;
    const int wid = tid >> 5;          // 0..3
    const int wm = wid >> 1;           // 0..1 -> 64-row half
    const int wn = wid & 1;            // 0..1 -> 64-col half

    if (tid == 0) {
        #pragma unroll
        for (int s = 0; s < NSTG; s++) {
            asm volatile("mbarrier.init.shared.b64 [%0], 1;"
                         :: "r"(mbF + 8 * s) : "memory");
            asm volatile("mbarrier.init.shared.b64 [%0], 128;"
                         :: "r"(mbE + 8 * s) : "memory");
        }
    }
    __syncthreads();

    float acc[4][8][4];
    #pragma unroll
    for (int i = 0; i < 4; i++)
        #pragma unroll
        for (int j = 0; j < 8; j++)
            #pragma unroll
            for (int k = 0; k < 4; k++) acc[i][j][k] = 0.f;

    auto bulk_load = [&](int chunk) {      // tid0 only
        const int st = chunk % NSTG;
        if (chunk >= NSTG)
            mbar_wait(mbE + 8 * st, (chunk / NSTG - 1) & 1);
        const unsigned mb = mbF + 8 * st;
        asm volatile("mbarrier.arrive.expect_tx.shared.b64 _, [%0], %1;"
                     :: "r"(mb), "r"((unsigned)STAGE_BYTES) : "memory");
        const unsigned s0 = sb + st * STAGE_BYTES;
        const size_t co = (size_t)chunk * TILE32;
        bulk8k(s0,          AH + co, mb);
        bulk8k(s0 + 8192,   AL + co, mb);
        bulk8k(s0 + 16384,  BH + co, mb);
        bulk8k(s0 + 24576,  BL + co, mb);
    };

    const int sfirst = wid & 1;       // warp-parity slice stagger
    auto compute = [&](int chunk) {
        const int st = chunk % NSTG;
        const unsigned s0 = sb + st * STAGE_BYTES;
        mbar_wait(mbF + 8 * st, (chunk / NSTG) & 1);
        #pragma unroll
        for (int si = 0; si < 2; si++) {
            const int s = si ^ sfirst;
            const int ch = 2 * s + (lane >> 4);
            unsigned AhF[4][4], AlF[4][4], BhF[4][4], BlF[4][4];
            #pragma unroll
            for (int mb = 0; mb < 4; mb++) {
                const int mr = wm * 64 + mb * 16 + (lane & 15);
                ldm4(AhF[mb], s0 + SWB32(mr, ch));
            }
            #pragma unroll
            for (int nb = 0; nb < 4; nb++) {
                const int nr = wn * 64 + nb * 16 + (lane & 15);
                ldm4(BhF[nb], s0 + 16384 + SWB32(nr, ch));
            }
            #pragma unroll
            for (int mb = 0; mb < 4; mb++)
                #pragma unroll
                for (int nb = 0; nb < 4; nb++) {
                    mma16816(acc[mb][nb * 2 + 0], AhF[mb], BhF[nb][0], BhF[nb][2]);
                    mma16816(acc[mb][nb * 2 + 1], AhF[mb], BhF[nb][1], BhF[nb][3]);
                }
            #pragma unroll
            for (int mb = 0; mb < 4; mb++) {
                const int mr = wm * 64 + mb * 16 + (lane & 15);
                ldm4(AlF[mb], s0 + 8192 + SWB32(mr, ch));
            }
            #pragma unroll
            for (int mb = 0; mb < 4; mb++)
                #pragma unroll
                for (int nb = 0; nb < 4; nb++) {
                    mma16816(acc[mb][nb * 2 + 0], AlF[mb], BhF[nb][0], BhF[nb][2]);
                    mma16816(acc[mb][nb * 2 + 1], AlF[mb], BhF[nb][1], BhF[nb][3]);
                }
            #pragma unroll
            for (int nb = 0; nb < 4; nb++) {
                const int nr = wn * 64 + nb * 16 + (lane & 15);
                ldm4(BlF[nb], s0 + 24576 + SWB32(nr, ch));
            }
            if (si == 1)                   // last smem read of this stage
                mbar_arrive(mbE + 8 * st);
            #pragma unroll
            for (int mb = 0; mb < 4; mb++)
                #pragma unroll
                for (int nb = 0; nb < 4; nb++) {
                    mma16816(acc[mb][nb * 2 + 0], AhF[mb], BlF[nb][0], BlF[nb][2]);
                    mma16816(acc[mb][nb * 2 + 1], AhF[mb], BlF[nb][1], BlF[nb][3]);
                }
        }
    };

    if (tid == 0) {
        bulk_load(0);
        if (nch > 1) bulk_load(1);
    }
    for (int i = 0; i < nch; i++) {
        if (tid == 0 && i + 2 < nch) bulk_load(i + 2);
        compute(i);
    }

    // ----- epilogue -----
    char *dH = 0, *dL = 0;
    int colr = col0;
    float* df = 0;
    long long ztile = 0;
    if (emode == 0) {
        df = Cf + (long long)bz * sC;
    } else if (emode == 1) {
        dH = D1H; dL = D1L; ztile = (long long)bz * sC;   // sC in tiles
    } else {                                  // qkv triple
        if (col0 < 1024)      { dH = D1H; dL = D1L; colr = col0; }
        else if (col0 < 2048) { dH = D2H; dL = D2L; colr = col0 - 1024; }
        else                  { dH = D3H; dL = D3L; colr = col0 - 2048; }
    }

    const int cbase = wn * 64 + 2 * (lane & 3);
    #pragma unroll
    for (int mb = 0; mb < 4; mb++) {
        #pragma unroll
        for (int half = 0; half < 2; half++) {
            const int r = row0 + wm * 64 + mb * 16 + (lane >> 2) + half * 8;
            const long long tb = dH ? (ztile + (long long)(r >> 7) * nchc) * TILE32 : 0;
            const int lr = r & 127;
            #pragma unroll
            for (int nb = 0; nb < 8; nb++) {
                const int cr = colr + cbase + nb * 8;    // region-relative (even)
                const int ca = col0 + cbase + nb * 8;    // absolute (bias)
                float vx = acc[mb][nb][half * 2 + 0] * alpha;
                float vy = acc[mb][nb][half * 2 + 1] * alpha;
                if (bias) { vx += bias[ca]; vy += bias[ca + 1]; }
                if (dH) {
                    unsigned short hx, lx, hy, ly;
                    split2(vx, hx, lx);
                    split2(vy, hy, ly);
                    const int byte = 2 * cr;             // multiple of 4
                    const unsigned off = (unsigned)(byte >> 6) * TILE32
                                       + SWB32(lr, (byte & 63) >> 4) + (byte & 15);
                    *(unsigned*)(dH + tb + off) = (unsigned)hx | ((unsigned)hy << 16);
                    *(unsigned*)(dL + tb + off) = (unsigned)lx | ((unsigned)ly << 16);
                } else {
                    *(float2*)(df + (long long)r * ldcf + cr) = make_float2(vx, vy);
                }
            }
        }
    }
}

// generic wrapper; revy=1 reverses row-tile order (longest k-limit first)
__global__ void __launch_bounds__(128, 2)
hmma_gemm(const char* __restrict__ AH, const char* __restrict__ AL,
          const char* __restrict__ BH, const char* __restrict__ BL,
          float* __restrict__ Cf,
          char* __restrict__ D1H, char* __restrict__ D1L,
          char* __restrict__ D2H, char* __restrict__ D2L,
          char* __restrict__ D3H, char* __restrict__ D3L,
          int ncha, int nchb, int ldcf, int nchc,
          long long sAt, long long sBt, long long sC,
          float alpha, const float* __restrict__ bias,
          int causal_skip, int klimit, int K, int emode, int revy)
{
    const int yy = revy ? (gridDim.y - 1 - blockIdx.y) : blockIdx.y;
    gemm_body(AH, AL, BH, BL, Cf, D1H, D1L, D2H, D2L, D3H, D3L,
              ncha, nchb, ldcf, nchc, sAt, sBt, sC, alpha, bias,
              causal_skip, klimit, K, emode,
              yy * 128, blockIdx.x * 128, blockIdx.z);
}

// fused scores + vw: grid (16, 16+8, 4). y<16 -> scores tile; y>=16 -> vw.
__global__ void __launch_bounds__(128, 2)
fused_scores_vw()
{
    const char *AH, *AL, *BH, *BL;
    float* Cf = 0;
    char *D1H = 0, *D1L = 0;
    int ncha, nchb, ldcf, nchc, causal_skip, emode, row0;
    long long sAt, sBt, sC;
    float alpha;
    if (blockIdx.y < 16) {          // scores = q @ k^T / sqrt(C)
        AH = (const char*)g_qH;  AL = (const char*)g_qL;
        BH = (const char*)g_kH;  BL = (const char*)g_kL;
        Cf = g_att;
        ncha = 32; nchb = 32; ldcf = 2048; nchc = 0;
        sAt = 16 * 32; sBt = 16 * 32; sC = (long long)2048 * 2048;
        alpha = 0.03125f; causal_skip = 1; emode = 0;
        row0 = blockIdx.y * 128;
    } else {                        // vw = Wp @ V^T
        AH = (const char*)g_wpH; AL = (const char*)g_wpL;
        BH = (const char*)g_vH;  BL = (const char*)g_vL;
        D1H = (char*)g_vwH; D1L = (char*)g_vwL;
        ncha = 32; nchb = 32; ldcf = 0; nchc = 64;
        sAt = 0; sBt = 16 * 32; sC = 8 * 64;
        alpha = 1.f; causal_skip = 0; emode = 1;
        row0 = (blockIdx.y - 16) * 128;
    }
    gemm_body(AH, AL, BH, BL, Cf, D1H, D1L, 0, 0, 0, 0,
              ncha, nchb, ldcf, nchc, sAt, sBt, sC, alpha, nullptr,
              causal_skip, 0, 1024, emode,
              row0, blockIdx.x * 128, blockIdx.z);
}

// ---------------------------------------------------------------------------
// fused input splits: rows [0,8192) = x, [8192,11264) = w_qkv,
// [11264,12288) = w_proj. All Cin=1024, ld=1024.
// ---------------------------------------------------------------------------
__global__ void split_inputs_kernel(const float* __restrict__ x,
                                    const float* __restrict__ wq,
                                    const float* __restrict__ wp)
{
    long long idx = (long long)blockIdx.x * blockDim.x + threadIdx.x;
    if (idx >= (long long)12288 * 128) return;
    int r = (int)(idx >> 7);
    const int c = (int)(idx & 127) * 8;

    const float* in;
    __nv_bfloat16 *outH, *outL;
    if (r < 8192)       { in = x;  outH = g_xH;  outL = g_xL; }
    else if (r < 11264) { in = wq; outH = g_wqH; outL = g_wqL; r -= 8192; }
    else                { in = wp; outH = g_wpH; outL = g_wpL; r -= 11264; }

    const float4 v0 = *(const float4*)(in + (long long)r * 1024 + c);
    const float4 v1 = *(const float4*)(in + (long long)r * 1024 + c + 4);
    float f[8] = {v0.x, v0.y, v0.z, v0.w, v1.x, v1.y, v1.z, v1.w};

    alignas(16) unsigned short h[8], l[8];
    #pragma unroll
    for (int j = 0; j < 8; j++) split2(f[j], h[j], l[j]);

    const size_t base = (size_t)(r >> 7) * 32 * TILE32;
    const int lr = r & 127;
    const int byte = 2 * c;                   // multiple of 16
    const unsigned off = (unsigned)(byte >> 6) * TILE32
                       + SWB32(lr, (byte & 63) >> 4);
    *(uint4*)((char*)outH + base + off) = *(uint4*)h;
    *(uint4*)((char*)outL + base + off) = *(uint4*)l;
}

// ---------------------------------------------------------------------------
// FMA-pipe exp for x <= 0 (MUFU EX2 is quarter-rate on B300).
// ---------------------------------------------------------------------------
__device__ __forceinline__ float fexp(float x) {
    float y = x * 1.4426950408889634f;
    float n = floorf(y);
    float f = y - n;
    float p = 0.000154035304f;
    p = fmaf(p, f, 0.00133335581f);
    p = fmaf(p, f, 0.00961812910f);
    p = fmaf(p, f, 0.0555041087f);
    p = fmaf(p, f, 0.240226507f);
    p = fmaf(p, f, 0.693147180f);
    p = fmaf(p, f, 1.0f);
    int ni = (int)n;
    if (ni < -126) return 0.f;
    return p * __int_as_float((ni + 127) << 23);
}

// ---------------------------------------------------------------------------
// causal softmax: fp32 scores -> (h,l) att planes. Warp-shuffle reductions
// (2 block barriers per reduction instead of 8).
// ---------------------------------------------------------------------------
__global__ void softmax_split_kernel(const float* __restrict__ att,
                                     __nv_bfloat16* __restrict__ attH,
                                     __nv_bfloat16* __restrict__ attL, int Tn)
{
    __shared__ float buf[2048];
    __shared__ float red[8];
    const int row = blockIdx.x;
    const int t = row % Tn;
    const float* p = att + (long long)row * Tn;
    const int tid = threadIdx.x;
    const int lane = tid & 31;
    const int wrp = tid >> 5;
    const int len = t + 1;
    const int lenR = (t & ~127) + 128;        // = row-tile boundary

    float m = -1e30f;
    for (int s = tid; s < len; s += 256) { float v = p[s]; buf[s] = v; m = fmaxf(m, v); }
    #pragma unroll
    for (int o = 16; o > 0; o >>= 1)
        m = fmaxf(m, __shfl_xor_sync(0xffffffffu, m, o));
    if (lane == 0) red[wrp] = m;
    __syncthreads();
    m = red[lane & 7];
    #pragma unroll
    for (int o = 4; o > 0; o >>= 1)
        m = fmaxf(m, __shfl_xor_sync(0xffffffffu, m, o));
    __syncthreads();

    float sum = 0.f;
    for (int s = tid; s < len; s += 256) {
        float e = fexp(buf[s] - m);
        buf[s] = e;
        sum += e;
    }
    #pragma unroll
    for (int o = 16; o > 0; o >>= 1)
        sum += __shfl_xor_sync(0xffffffffu, sum, o);
    if (lane == 0) red[wrp] = sum;
    __syncthreads();
    sum = red[lane & 7];
    #pragma unroll
    for (int o = 4; o > 0; o >>= 1)
        sum += __shfl_xor_sync(0xffffffffu, sum, o);
    const float inv = 1.f / sum;

    const int s8 = tid * 8;                   // 8 tokens per thread
    if (s8 < lenR) {
        alignas(16) unsigned short h[8], l[8];
        #pragma unroll
        for (int j = 0; j < 8; j++) {
            const int s = s8 + j;
            const float e = (s < len) ? buf[s] * inv : 0.f;
            split2(e, h[j], l[j]);
        }
        const size_t base = (size_t)(row >> 7) * 64 * TILE32;
        const int lr = row & 127;
        const int byte = 2 * s8;
        const unsigned off = (unsigned)(byte >> 6) * TILE32
                           + SWB32(lr, (byte & 63) >> 4);
        *(uint4*)((char*)attH + base + off) = *(uint4*)h;
        *(uint4*)((char*)attL + base + off) = *(uint4*)l;
    }
}

// ---------------------------------------------------------------------------
extern "C" void kernel_launch(void* const* d_in, const int* in_sizes, int n_in,
                              void* d_out, int out_size)
{
    const float* x      = (const float*)d_in[0];
    const float* w_qkv  = (const float*)d_in[1];
    const float* b_qkv  = (const float*)d_in[2];
    const float* w_proj = (const float*)d_in[3];
    const float* b_proj = (const float*)d_in[4];
    float* out = (float*)d_out;

    float *att;
    __nv_bfloat16 *xH, *xL, *wqH, *wqL;
    __nv_bfloat16 *qH, *qL, *kH, *kL, *vH, *vL, *vwH, *vwL, *aH, *aL;
    cudaGetSymbolAddress((void**)&att, g_att);
    cudaGetSymbolAddress((void**)&xH,  g_xH);  cudaGetSymbolAddress((void**)&xL,  g_xL);
    cudaGetSymbolAddress((void**)&wqH, g_wqH); cudaGetSymbolAddress((void**)&wqL, g_wqL);
    cudaGetSymbolAddress((void**)&qH,  g_qH);  cudaGetSymbolAddress((void**)&qL,  g_qL);
    cudaGetSymbolAddress((void**)&kH,  g_kH);  cudaGetSymbolAddress((void**)&kL,  g_kL);
    cudaGetSymbolAddress((void**)&vH,  g_vH);  cudaGetSymbolAddress((void**)&vL,  g_vL);
    cudaGetSymbolAddress((void**)&vwH, g_vwH); cudaGetSymbolAddress((void**)&vwL, g_vwL);
    cudaGetSymbolAddress((void**)&aH,  g_aH);  cudaGetSymbolAddress((void**)&aL,  g_aL);

    cudaFuncSetAttribute(hmma_gemm,
        cudaFuncAttributeMaxDynamicSharedMemorySize, GEMM_SMEM);
    cudaFuncSetAttribute(fused_scores_vw,
        cudaFuncAttributeMaxDynamicSharedMemorySize, GEMM_SMEM);

    // 0) fused input splits (x, w_qkv, w_proj)
    split_inputs_kernel<<<(12288 * 128 + 255) / 256, 256>>>(x, w_qkv, w_proj);

    // 1) qkv GEMM -> q / k / v planes
    hmma_gemm<<<dim3(3 * C / 128, M / 128, 1), 128, GEMM_SMEM>>>(
        (const char*)xH, (const char*)xL, (const char*)wqH, (const char*)wqL,
        nullptr, (char*)qH, (char*)qL, (char*)kH, (char*)kL, (char*)vH, (char*)vL,
        32, 32, 0, 32, 0, 0, 0,
        1.f, b_qkv, 0, 0, C, 2, 0);

    // 2+3) FUSED: scores (causal, fp32 att) + vw = Wp @ V^T (plane out)
    fused_scores_vw<<<dim3(T / 128, T / 128 + C / 128, Bb), 128, GEMM_SMEM>>>();

    // 4) softmax -> att planes (tile-bounded writes)
    softmax_split_kernel<<<M, 256>>>(att, aH, aL, T);

    // 5) out = att @ VWt^T + b_proj  (k-limited; LONGEST row tiles first)
    hmma_gemm<<<dim3(C / 128, T / 128, Bb), 128, GEMM_SMEM>>>(
        (const char*)aH, (const char*)aL, (const char*)vwH, (const char*)vwL,
        out, nullptr, nullptr, nullptr, nullptr, nullptr, nullptr,
        64, 64, C, 0,
        16 * 64, 8 * 64, (long long)T * C,
        1.f, b_proj, 0, 1, T, 0, 1);
}

// round 17
// speedup vs baseline: 1.1930x; 1.0478x over previous
#include <cuda_runtime.h>
#include <cuda_bf16.h>
#include <math.h>

// ---------------------------------------------------------------------------
// Causal self-attention block via mma.sync (HMMA bf16) on sm_103.
// fp32 emulation by SEGMENTED 2-plane bf16 split (H,L over original K);
// GEMM computes AhBh + AlBh + AhBl (drops only AlBl ~2^-18).
// R17: tail-of-chunk full-wait + first-slice Ah/Bh fragment preload — the
// next chunk's mbar wait and LDSM latency hide under the current chunk's
// MMA drain, removing the serial chunk-head bubble.
// ---------------------------------------------------------------------------

static const int Bb = 4, T = 2048, C = 1024;
static const int M = Bb * T;          // 8192

#define TILE32 8192                   // 128 rows x 32 k x 2B

// fp32 intermediates
__device__ float g_att[(size_t)4 * 2048 * 2048];
// (H,L) bf16 planes, tiled [row_stripe][chunk][8KB swizzled]
__device__ __nv_bfloat16 g_xH [(size_t)8192 * 1024];
__device__ __nv_bfloat16 g_xL [(size_t)8192 * 1024];
__device__ __nv_bfloat16 g_wqH[(size_t)3072 * 1024];
__device__ __nv_bfloat16 g_wqL[(size_t)3072 * 1024];
__device__ __nv_bfloat16 g_wpH[(size_t)1024 * 1024];
__device__ __nv_bfloat16 g_wpL[(size_t)1024 * 1024];
__device__ __nv_bfloat16 g_qH [(size_t)8192 * 1024];
__device__ __nv_bfloat16 g_qL [(size_t)8192 * 1024];
__device__ __nv_bfloat16 g_kH [(size_t)8192 * 1024];
__device__ __nv_bfloat16 g_kL [(size_t)8192 * 1024];
__device__ __nv_bfloat16 g_vH [(size_t)8192 * 1024];
__device__ __nv_bfloat16 g_vL [(size_t)8192 * 1024];
__device__ __nv_bfloat16 g_vwH[(size_t)4 * 1024 * 2048];
__device__ __nv_bfloat16 g_vwL[(size_t)4 * 1024 * 2048];
__device__ __nv_bfloat16 g_aH [(size_t)8192 * 2048];
__device__ __nv_bfloat16 g_aL [(size_t)8192 * 2048];

// swizzle for 64-byte rows (32 bf16): 16B slot c (0..3) -> c ^ ((r>>1)&3)
#define SWB32(r, c) ((unsigned)((r) * 64 + ((((c) ^ (((r) >> 1) & 3)) & 3) << 4)))

__device__ __forceinline__ void ldm4(unsigned* r, unsigned addr) {
    asm volatile("ldmatrix.sync.aligned.m8n8.x4.shared.b16 {%0,%1,%2,%3}, [%4];"
        : "=r"(r[0]), "=r"(r[1]), "=r"(r[2]), "=r"(r[3]) : "r"(addr));
}
__device__ __forceinline__ void mma16816(float* d, const unsigned* a,
                                         unsigned b0, unsigned b1) {
    asm volatile(
        "mma.sync.aligned.m16n8k16.row.col.f32.bf16.bf16.f32 "
        "{%0,%1,%2,%3}, {%4,%5,%6,%7}, {%8,%9}, {%0,%1,%2,%3};"
        : "+f"(d[0]), "+f"(d[1]), "+f"(d[2]), "+f"(d[3])
        : "r"(a[0]), "r"(a[1]), "r"(a[2]), "r"(a[3]), "r"(b0), "r"(b1));
}
__device__ __forceinline__ void bulk8k(unsigned sdst, const void* g, unsigned mb) {
    unsigned sz = TILE32;
    asm volatile(
        "cp.async.bulk.shared::cluster.global.mbarrier::complete_tx::bytes "
        "[%0], [%1], %2, [%3];"
        :: "r"(sdst), "l"(__cvta_generic_to_global(g)), "r"(sz), "r"(mb)
        : "memory");
}
__device__ __forceinline__ void mbar_wait(unsigned mbar, unsigned parity) {
    asm volatile(
        "{\n\t.reg .pred P;\n\t"
        "LW_%=:\n\t"
        "mbarrier.try_wait.parity.acquire.cta.shared::cta.b64 P, [%0], %1, 0x989680;\n\t"
        "@P bra.uni LD_%=;\n\t"
        "bra.uni LW_%=;\n\t"
        "LD_%=:\n\t}"
        :: "r"(mbar), "r"(parity) : "memory");
}
__device__ __forceinline__ void mbar_arrive(unsigned mbar) {
    asm volatile("mbarrier.arrive.release.cta.shared.b64 _, [%0];"
                 :: "r"(mbar) : "memory");
}

__device__ __forceinline__ void split2(float v, unsigned short& h, unsigned short& l) {
    __nv_bfloat16 hb = __float2bfloat16(v);
    __nv_bfloat16 lb = __float2bfloat16(v - __bfloat162float(hb));
    h = __bfloat16_as_ushort(hb);
    l = __bfloat16_as_ushort(lb);
}

#define STAGE_BYTES 32768 // Ah 8K + Al 8K + Bh 8K + Bl 8K
#define NSTG 3
#define GEMM_SMEM (NSTG * STAGE_BYTES + 128)

// ---------------------------------------------------------------------------
// GEMM body: 128 threads, 4 warps, 64x64 warp tiles over a 128x128 CTA tile;
// 3-stage bulk pipeline; tail-of-chunk wait + first-slice frag preload.
// emode 0: fp32 out; 1: plane out D1; 2: qkv triple D1/D2/D3.
// ---------------------------------------------------------------------------
__device__ __forceinline__ void gemm_body(
    const char* AH, const char* AL, const char* BH, const char* BL,
    float* Cf, char* D1H, char* D1L, char* D2H, char* D2L,
    char* D3H, char* D3L,
    int ncha, int nchb, int ldcf, int nchc,
    long long sAt, long long sBt, long long sC,
    float alpha, const float* bias,
    int causal_skip, int klimit, int K, int emode,
    int row0, int col0, int bz)
{
    if (causal_skip && col0 > row0) return;              // strictly-upper tiles
    const int kend = klimit ? min(K, row0 + 128) : K;
    const int nch = kend >> 5;                           // 32-k chunks

    const long long aoff = ((long long)bz * sAt + (row0 >> 7) * ncha) * TILE32;
    const long long boff = ((long long)bz * sBt + (col0 >> 7) * nchb) * TILE32;
    AH += aoff; AL += aoff; BH += boff; BL += boff;

    extern __shared__ __align__(128) unsigned char smem[];
    const unsigned sb = (unsigned)__cvta_generic_to_shared(smem);
    const unsigned mbF = sb + NSTG * STAGE_BYTES;        // full barriers
    const unsigned mbE = mbF + 8 * NSTG;                 // empty barriers

    const int tid = threadIdx.x;
    const int lane = tid & 31;
    const int wid = tid >> 5;          // 0..3
    const int wm = wid >> 1;           // 0..1 -> 64-row half
    const int wn = wid & 1;            // 0..1 -> 64-col half

    if (tid == 0) {
        #pragma unroll
        for (int s = 0; s < NSTG; s++) {
            asm volatile("mbarrier.init.shared.b64 [%0], 1;"
                         :: "r"(mbF + 8 * s) : "memory");
            asm volatile("mbarrier.init.shared.b64 [%0], 128;"
                         :: "r"(mbE + 8 * s) : "memory");
        }
    }
    __syncthreads();

    float acc[4][8][4];
    #pragma unroll
    for (int i = 0; i < 4; i++)
        #pragma unroll
        for (int j = 0; j < 8; j++)
            #pragma unroll
            for (int k = 0; k < 4; k++) acc[i][j][k] = 0.f;

    auto bulk_load = [&](int chunk) {      // tid0 only
        const int st = chunk % NSTG;
        if (chunk >= NSTG)
            mbar_wait(mbE + 8 * st, (chunk / NSTG - 1) & 1);
        const unsigned mb = mbF + 8 * st;
        asm volatile("mbarrier.arrive.expect_tx.shared.b64 _, [%0], %1;"
                     :: "r"(mb), "r"((unsigned)STAGE_BYTES) : "memory");
        const unsigned s0 = sb + st * STAGE_BYTES;
        const size_t co = (size_t)chunk * TILE32;
        bulk8k(s0,          AH + co, mb);
        bulk8k(s0 + 8192,   AL + co, mb);
        bulk8k(s0 + 16384,  BH + co, mb);
        bulk8k(s0 + 24576,  BL + co, mb);
    };

    const int sfirst = wid & 1;       // warp-parity slice stagger
    const int chf = 2 * sfirst + (lane >> 4);   // first slice's 16B slot

    // persistent preloaded first-slice fragments for the upcoming chunk
    unsigned pAh[4][4], pBh[4][4];

    auto preload = [&](int chunk) {   // wait stage full, load slice-sfirst Ah/Bh
        const int st = chunk % NSTG;
        mbar_wait(mbF + 8 * st, (chunk / NSTG) & 1);
        const unsigned s0 = sb + st * STAGE_BYTES;
        #pragma unroll
        for (int mb = 0; mb < 4; mb++) {
            const int mr = wm * 64 + mb * 16 + (lane & 15);
            ldm4(pAh[mb], s0 + SWB32(mr, chf));
        }
        #pragma unroll
        for (int nb = 0; nb < 4; nb++) {
            const int nr = wn * 64 + nb * 16 + (lane & 15);
            ldm4(pBh[nb], s0 + 16384 + SWB32(nr, chf));
        }
    };

    // compute chunk (full barrier already passed; pAh/pBh hold slice sfirst)
    auto compute = [&](int chunk) {
        const int st = chunk % NSTG;
        const unsigned s0 = sb + st * STAGE_BYTES;
        #pragma unroll
        for (int si = 0; si < 2; si++) {
            const int s = si ^ sfirst;
            const int ch = 2 * s + (lane >> 4);
            unsigned AhF[4][4], AlF[4][4], BhF[4][4], BlF[4][4];
            if (si == 0) {                 // use preloaded fragments
                #pragma unroll
                for (int mb = 0; mb < 4; mb++)
                    #pragma unroll
                    for (int q = 0; q < 4; q++) AhF[mb][q] = pAh[mb][q];
                #pragma unroll
                for (int nb = 0; nb < 4; nb++)
                    #pragma unroll
                    for (int q = 0; q < 4; q++) BhF[nb][q] = pBh[nb][q];
            } else {
                #pragma unroll
                for (int mb = 0; mb < 4; mb++) {
                    const int mr = wm * 64 + mb * 16 + (lane & 15);
                    ldm4(AhF[mb], s0 + SWB32(mr, ch));
                }
                #pragma unroll
                for (int nb = 0; nb < 4; nb++) {
                    const int nr = wn * 64 + nb * 16 + (lane & 15);
                    ldm4(BhF[nb], s0 + 16384 + SWB32(nr, ch));
                }
            }
            #pragma unroll
            for (int mb = 0; mb < 4; mb++)
                #pragma unroll
                for (int nb = 0; nb < 4; nb++) {
                    mma16816(acc[mb][nb * 2 + 0], AhF[mb], BhF[nb][0], BhF[nb][2]);
                    mma16816(acc[mb][nb * 2 + 1], AhF[mb], BhF[nb][1], BhF[nb][3]);
                }
            #pragma unroll
            for (int mb = 0; mb < 4; mb++) {
                const int mr = wm * 64 + mb * 16 + (lane & 15);
                ldm4(AlF[mb], s0 + 8192 + SWB32(mr, ch));
            }
            #pragma unroll
            for (int mb = 0; mb < 4; mb++)
                #pragma unroll
                for (int nb = 0; nb < 4; nb++) {
                    mma16816(acc[mb][nb * 2 + 0], AlF[mb], BhF[nb][0], BhF[nb][2]);
                    mma16816(acc[mb][nb * 2 + 1], AlF[mb], BhF[nb][1], BhF[nb][3]);
                }
            #pragma unroll
            for (int nb = 0; nb < 4; nb++) {
                const int nr = wn * 64 + nb * 16 + (lane & 15);
                ldm4(BlF[nb], s0 + 24576 + SWB32(nr, ch));
            }
            if (si == 1)                   // last smem read of this stage
                mbar_arrive(mbE + 8 * st);
            #pragma unroll
            for (int mb = 0; mb < 4; mb++)
                #pragma unroll
                for (int nb = 0; nb < 4; nb++) {
                    mma16816(acc[mb][nb * 2 + 0], AhF[mb], BlF[nb][0], BlF[nb][2]);
                    mma16816(acc[mb][nb * 2 + 1], AhF[mb], BlF[nb][1], BlF[nb][3]);
                }
        }
    };

    if (tid == 0) {
        bulk_load(0);
        if (nch > 1) bulk_load(1);
    }
    preload(0);                        // head of first chunk only
    for (int i = 0; i < nch; i++) {
        if (tid == 0 && i + 2 < nch) bulk_load(i + 2);
        compute(i);
        // tail-of-chunk: wait next stage + preload its first-slice frags,
        // hidden under this chunk's MMA drain.
        if (i + 1 < nch) preload(i + 1);
    }

    // ----- epilogue -----
    char *dH = 0, *dL = 0;
    int colr = col0;
    float* df = 0;
    long long ztile = 0;
    if (emode == 0) {
        df = Cf + (long long)bz * sC;
    } else if (emode == 1) {
        dH = D1H; dL = D1L; ztile = (long long)bz * sC;   // sC in tiles
    } else {                                  // qkv triple
        if (col0 < 1024)      { dH = D1H; dL = D1L; colr = col0; }
        else if (col0 < 2048) { dH = D2H; dL = D2L; colr = col0 - 1024; }
        else                  { dH = D3H; dL = D3L; colr = col0 - 2048; }
    }

    const int cbase = wn * 64 + 2 * (lane & 3);
    #pragma unroll
    for (int mb = 0; mb < 4; mb++) {
        #pragma unroll
        for (int half = 0; half < 2; half++) {
            const int r = row0 + wm * 64 + mb * 16 + (lane >> 2) + half * 8;
            const long long tb = dH ? (ztile + (long long)(r >> 7) * nchc) * TILE32 : 0;
            const int lr = r & 127;
            #pragma unroll
            for (int nb = 0; nb < 8; nb++) {
                const int cr = colr + cbase + nb * 8;    // region-relative (even)
                const int ca = col0 + cbase + nb * 8;    // absolute (bias)
                float vx = acc[mb][nb][half * 2 + 0] * alpha;
                float vy = acc[mb][nb][half * 2 + 1] * alpha;
                if (bias) { vx += bias[ca]; vy += bias[ca + 1]; }
                if (dH) {
                    unsigned short hx, lx, hy, ly;
                    split2(vx, hx, lx);
                    split2(vy, hy, ly);
                    const int byte = 2 * cr;             // multiple of 4
                    const unsigned off = (unsigned)(byte >> 6) * TILE32
                                       + SWB32(lr, (byte & 63) >> 4) + (byte & 15);
                    *(unsigned*)(dH + tb + off) = (unsigned)hx | ((unsigned)hy << 16);
                    *(unsigned*)(dL + tb + off) = (unsigned)lx | ((unsigned)ly << 16);
                } else {
                    *(float2*)(df + (long long)r * ldcf + cr) = make_float2(vx, vy);
                }
            }
        }
    }
}

// generic wrapper; revy=1 reverses row-tile order (longest k-limit first)
__global__ void __launch_bounds__(128, 2)
hmma_gemm(const char* __restrict__ AH, const char* __restrict__ AL,
          const char* __restrict__ BH, const char* __restrict__ BL,
          float* __restrict__ Cf,
          char* __restrict__ D1H, char* __restrict__ D1L,
          char* __restrict__ D2H, char* __restrict__ D2L,
          char* __restrict__ D3H, char* __restrict__ D3L,
          int ncha, int nchb, int ldcf, int nchc,
          long long sAt, long long sBt, long long sC,
          float alpha, const float* __restrict__ bias,
          int causal_skip, int klimit, int K, int emode, int revy)
{
    const int yy = revy ? (gridDim.y - 1 - blockIdx.y) : blockIdx.y;
    gemm_body(AH, AL, BH, BL, Cf, D1H, D1L, D2H, D2L, D3H, D3L,
              ncha, nchb, ldcf, nchc, sAt, sBt, sC, alpha, bias,
              causal_skip, klimit, K, emode,
              yy * 128, blockIdx.x * 128, blockIdx.z);
}

// fused scores + vw: grid (16, 16+8, 4). y<16 -> scores tile; y>=16 -> vw.
__global__ void __launch_bounds__(128, 2)
fused_scores_vw()
{
    const char *AH, *AL, *BH, *BL;
    float* Cf = 0;
    char *D1H = 0, *D1L = 0;
    int ncha, nchb, ldcf, nchc, causal_skip, emode, row0;
    long long sAt, sBt, sC;
    float alpha;
    if (blockIdx.y < 16) {          // scores = q @ k^T / sqrt(C)
        AH = (const char*)g_qH;  AL = (const char*)g_qL;
        BH = (const char*)g_kH;  BL = (const char*)g_kL;
        Cf = g_att;
        ncha = 32; nchb = 32; ldcf = 2048; nchc = 0;
        sAt = 16 * 32; sBt = 16 * 32; sC = (long long)2048 * 2048;
        alpha = 0.03125f; causal_skip = 1; emode = 0;
        row0 = blockIdx.y * 128;
    } else {                        // vw = Wp @ V^T
        AH = (const char*)g_wpH; AL = (const char*)g_wpL;
        BH = (const char*)g_vH;  BL = (const char*)g_vL;
        D1H = (char*)g_vwH; D1L = (char*)g_vwL;
        ncha = 32; nchb = 32; ldcf = 0; nchc = 64;
        sAt = 0; sBt = 16 * 32; sC = 8 * 64;
        alpha = 1.f; causal_skip = 0; emode = 1;
        row0 = (blockIdx.y - 16) * 128;
    }
    gemm_body(AH, AL, BH, BL, Cf, D1H, D1L, 0, 0, 0, 0,
              ncha, nchb, ldcf, nchc, sAt, sBt, sC, alpha, nullptr,
              causal_skip, 0, 1024, emode,
              row0, blockIdx.x * 128, blockIdx.z);
}

// ---------------------------------------------------------------------------
// fused input splits: rows [0,8192) = x, [8192,11264) = w_qkv,
// [11264,12288) = w_proj. All Cin=1024, ld=1024.
// ---------------------------------------------------------------------------
__global__ void split_inputs_kernel(const float* __restrict__ x,
                                    const float* __restrict__ wq,
                                    const float* __restrict__ wp)
{
    long long idx = (long long)blockIdx.x * blockDim.x + threadIdx.x;
    if (idx >= (long long)12288 * 128) return;
    int r = (int)(idx >> 7);
    const int c = (int)(idx & 127) * 8;

    const float* in;
    __nv_bfloat16 *outH, *outL;
    if (r < 8192)       { in = x;  outH = g_xH;  outL = g_xL; }
    else if (r < 11264) { in = wq; outH = g_wqH; outL = g_wqL; r -= 8192; }
    else                { in = wp; outH = g_wpH; outL = g_wpL; r -= 11264; }

    const float4 v0 = *(const float4*)(in + (long long)r * 1024 + c);
    const float4 v1 = *(const float4*)(in + (long long)r * 1024 + c + 4);
    float f[8] = {v0.x, v0.y, v0.z, v0.w, v1.x, v1.y, v1.z, v1.w};

    alignas(16) unsigned short h[8], l[8];
    #pragma unroll
    for (int j = 0; j < 8; j++) split2(f[j], h[j], l[j]);

    const size_t base = (size_t)(r >> 7) * 32 * TILE32;
    const int lr = r & 127;
    const int byte = 2 * c;                   // multiple of 16
    const unsigned off = (unsigned)(byte >> 6) * TILE32
                       + SWB32(lr, (byte & 63) >> 4);
    *(uint4*)((char*)outH + base + off) = *(uint4*)h;
    *(uint4*)((char*)outL + base + off) = *(uint4*)l;
}

// ---------------------------------------------------------------------------
// FMA-pipe exp for x <= 0 (MUFU EX2 is quarter-rate on B300).
// ---------------------------------------------------------------------------
__device__ __forceinline__ float fexp(float x) {
    float y = x * 1.4426950408889634f;
    float n = floorf(y);
    float f = y - n;
    float p = 0.000154035304f;
    p = fmaf(p, f, 0.00133335581f);
    p = fmaf(p, f, 0.00961812910f);
    p = fmaf(p, f, 0.0555041087f);
    p = fmaf(p, f, 0.240226507f);
    p = fmaf(p, f, 0.693147180f);
    p = fmaf(p, f, 1.0f);
    int ni = (int)n;
    if (ni < -126) return 0.f;
    return p * __int_as_float((ni + 127) << 23);
}

// ---------------------------------------------------------------------------
// causal softmax: fp32 scores -> (h,l) att planes. Warp-shuffle reductions.
// ---------------------------------------------------------------------------
__global__ void softmax_split_kernel(const float* __restrict__ att,
                                     __nv_bfloat16* __restrict__ attH,
                                     __nv_bfloat16* __restrict__ attL, int Tn)
{
    __shared__ float buf[2048];
    __shared__ float red[8];
    const int row = blockIdx.x;
    const int t = row % Tn;
    const float* p = att + (long long)row * Tn;
    const int tid = threadIdx.x;
    const int lane = tid & 31;
    const int wrp = tid >> 5;
    const int len = t + 1;
    const int lenR = (t & ~127) + 128;        // = row-tile boundary

    float m = -1e30f;
    for (int s = tid; s < len; s += 256) { float v = p[s]; buf[s] = v; m = fmaxf(m, v); }
    #pragma unroll
    for (int o = 16; o > 0; o >>= 1)
        m = fmaxf(m, __shfl_xor_sync(0xffffffffu, m, o));
    if (lane == 0) red[wrp] = m;
    __syncthreads();
    m = red[lane & 7];
    #pragma unroll
    for (int o = 4; o > 0; o >>= 1)
        m = fmaxf(m, __shfl_xor_sync(0xffffffffu, m, o));
    __syncthreads();

    float sum = 0.f;
    for (int s = tid; s < len; s += 256) {
        float e = fexp(buf[s] - m);
        buf[s] = e;
        sum += e;
    }
    #pragma unroll
    for (int o = 16; o > 0; o >>= 1)
        sum += __shfl_xor_sync(0xffffffffu, sum, o);
    if (lane == 0) red[wrp] = sum;
    __syncthreads();
    sum = red[lane & 7];
    #pragma unroll
    for (int o = 4; o > 0; o >>= 1)
        sum += __shfl_xor_sync(0xffffffffu, sum, o);
    const float inv = 1.f / sum;

    const int s8 = tid * 8;                   // 8 tokens per thread
    if (s8 < lenR) {
        alignas(16) unsigned short h[8], l[8];
        #pragma unroll
        for (int j = 0; j < 8; j++) {
            const int s = s8 + j;
            const float e = (s < len) ? buf[s] * inv : 0.f;
            split2(e, h[j], l[j]);
        }
        const size_t base = (size_t)(row >> 7) * 64 * TILE32;
        const int lr = row & 127;
        const int byte = 2 * s8;
        const unsigned off = (unsigned)(byte >> 6) * TILE32
                           + SWB32(lr, (byte & 63) >> 4);
        *(uint4*)((char*)attH + base + off) = *(uint4*)h;
        *(uint4*)((char*)attL + base + off) = *(uint4*)l;
    }
}

// ---------------------------------------------------------------------------
extern "C" void kernel_launch(void* const* d_in, const int* in_sizes, int n_in,
                              void* d_out, int out_size)
{
    const float* x      = (const float*)d_in[0];
    const float* w_qkv  = (const float*)d_in[1];
    const float* b_qkv  = (const float*)d_in[2];
    const float* w_proj = (const float*)d_in[3];
    const float* b_proj = (const float*)d_in[4];
    float* out = (float*)d_out;

    float *att;
    __nv_bfloat16 *xH, *xL, *wqH, *wqL;
    __nv_bfloat16 *qH, *qL, *kH, *kL, *vH, *vL, *vwH, *vwL, *aH, *aL;
    cudaGetSymbolAddress((void**)&att, g_att);
    cudaGetSymbolAddress((void**)&xH,  g_xH);  cudaGetSymbolAddress((void**)&xL,  g_xL);
    cudaGetSymbolAddress((void**)&wqH, g_wqH); cudaGetSymbolAddress((void**)&wqL, g_wqL);
    cudaGetSymbolAddress((void**)&qH,  g_qH);  cudaGetSymbolAddress((void**)&qL,  g_qL);
    cudaGetSymbolAddress((void**)&kH,  g_kH);  cudaGetSymbolAddress((void**)&kL,  g_kL);
    cudaGetSymbolAddress((void**)&vH,  g_vH);  cudaGetSymbolAddress((void**)&vL,  g_vL);
    cudaGetSymbolAddress((void**)&vwH, g_vwH); cudaGetSymbolAddress((void**)&vwL, g_vwL);
    cudaGetSymbolAddress((void**)&aH,  g_aH);  cudaGetSymbolAddress((void**)&aL,  g_aL);

    cudaFuncSetAttribute(hmma_gemm,
        cudaFuncAttributeMaxDynamicSharedMemorySize, GEMM_SMEM);
    cudaFuncSetAttribute(fused_scores_vw,
        cudaFuncAttributeMaxDynamicSharedMemorySize, GEMM_SMEM);

    // 0) fused input splits (x, w_qkv, w_proj)
    split_inputs_kernel<<<(12288 * 128 + 255) / 256, 256>>>(x, w_qkv, w_proj);

    // 1) qkv GEMM -> q / k / v planes
    hmma_gemm<<<dim3(3 * C / 128, M / 128, 1), 128, GEMM_SMEM>>>(
        (const char*)xH, (const char*)xL, (const char*)wqH, (const char*)wqL,
        nullptr, (char*)qH, (char*)qL, (char*)kH, (char*)kL, (char*)vH, (char*)vL,
        32, 32, 0, 32, 0, 0, 0,
        1.f, b_qkv, 0, 0, C, 2, 0);

    // 2+3) FUSED: scores (causal, fp32 att) + vw = Wp @ V^T (plane out)
    fused_scores_vw<<<dim3(T / 128, T / 128 + C / 128, Bb), 128, GEMM_SMEM>>>();

    // 4) softmax -> att planes (tile-bounded writes)
    softmax_split_kernel<<<M, 256>>>(att, aH, aL, T);

    // 5) out = att @ VWt^T + b_proj  (k-limited; LONGEST row tiles first)
    hmma_gemm<<<dim3(C / 128, T / 128, Bb), 128, GEMM_SMEM>>>(
        (const char*)aH, (const char*)aL, (const char*)vwH, (const char*)vwL,
        out, nullptr, nullptr, nullptr, nullptr, nullptr, nullptr,
        64, 64, C, 0,
        16 * 64, 8 * 64, (long long)T * C,
        1.f, b_proj, 0, 1, T, 0, 1);
}